// round 7
// baseline (speedup 1.0000x reference)
#include <cuda_runtime.h>
#include <math.h>

#define B   32
#define EN  256
#define DX  512
#define DZ  256
#define DM  256
#define H   8
#define LQ  256   // active queries: l in [256,512)
#define NB  256   // persistent blocks; launch_bounds(256,2) -> 296 slots >= 256, all co-resident

// scratch (device globals; no allocation allowed)
__device__ __align__(16) float g_Q0[LQ*DM];      // Q0[l'][d] = Qp[256+l']@Wq^T + bq
__device__ __align__(16) float g_P0[B*DM];       // P0[b][d]  = pe[b]@Wq^T
__device__ __align__(16) float g_GQT[H*DM*LQ];   // [h][e][l']
__device__ __align__(16) float g_GPb[B*H*DM];    // [b][h][e]
// barrier state: one flag per block on its own 128B line (NO same-address atomics)
__device__ volatile unsigned g_flags[NB * 32];
__device__ volatile unsigned g_release;

// Distributed-flag grid barrier. All NB blocks co-resident (guaranteed by launch bounds).
__device__ __forceinline__ void gridbar(unsigned phase, int bid, int tid) {
    __syncthreads();
    if (bid == 0) {
        if (tid == 0) { __threadfence(); g_flags[0] = phase; }
        // each thread watches exactly one block's flag (NB == blockDim)
        while (g_flags[tid * 32] < phase) __nanosleep(32);
        __syncthreads();
        if (tid == 0) { __threadfence(); g_release = phase; }
        __syncthreads();
    } else {
        if (tid == 0) {
            __threadfence();
            g_flags[bid * 32] = phase;
            while (g_release < phase) __nanosleep(32);
        }
        __syncthreads();
    }
}

__global__ __launch_bounds__(256, 2) void k_fused(
    const float* __restrict__ state, const float* __restrict__ obs,
    const float* __restrict__ Qp, const float* __restrict__ Wq,
    const float* __restrict__ bq, const float* __restrict__ Wk,
    float* __restrict__ ns, float* __restrict__ att)
{
    __shared__ union {
        float rowS[32 * DM];                              // phase 0a: 32KB
        float gk[8192 + 1024];                            // phase 1:  36KB
        struct { float gps[H*DM]; float red[17*256];
                 float sgp[8]; float wsh[32]; } d;        // phase 2: ~25.8KB
    } sm;

    const int bid = blockIdx.x;
    const int tid = threadIdx.x;
    const int lane = tid & 31;
    const int wid = tid >> 5;
    const int gw = bid * 8 + wid;         // global warp id 0..2047

    // ================= Phase 0a: Q0 / P0 projection (blocks 0..71) =================
    if (bid < 72) {
        int rt = bid >> 3, dt = bid & 7;      // rt 0..8 (32 rows), dt 0..7 (32 d)
        const float nl = -(logf(10000.0f) / (float)DM);
        #pragma unroll
        for (int k = 0; k < 32; k++) {
            int lin = k * 256 + tid;
            int r = lin >> 8, c = lin & 255;
            int gi = rt * 32 + r;
            float v;
            if (gi < 256) {
                v = Qp[(256 + gi) * DM + c];
            } else {
                int p = gi - 256;             // pe row (= batch index)
                int i = c >> 1;
                float dv = expf(nl * (float)(2 * i));
                float arg = (float)p * dv;
                v = (c & 1) ? cosf(arg) : sinf(arg);
            }
            sm.rowS[r * DM + c] = v;
        }
        __syncthreads();

        int d = dt * 32 + lane;
        int rbase = wid * 4;
        float bias = (rt < 8) ? bq[d] : 0.0f;   // pe rows (P0) exclude bq
        float acc[4];
        #pragma unroll
        for (int r = 0; r < 4; r++) acc[r] = bias;

        const float4* Wq4 = (const float4*)(Wq + (size_t)d * DM);
        #pragma unroll 8
        for (int c4 = 0; c4 < 64; c4++) {
            float4 w4 = Wq4[c4];
            #pragma unroll
            for (int r = 0; r < 4; r++) {
                float4 r4 = ((const float4*)&sm.rowS[(rbase + r) * DM])[c4];
                acc[r] += r4.x * w4.x + r4.y * w4.y + r4.z * w4.z + r4.w * w4.w;
            }
        }
        #pragma unroll
        for (int r = 0; r < 4; r++) {
            int gi = rt * 32 + rbase + r;
            if (gi < 256) g_Q0[gi * DM + d] = acc[r];
            else          g_P0[(gi - 256) * DM + d] = acc[r];
        }
    }

    // ================= Phase 0b: statically-partitioned streaming (no atomics) ======
    // att zero-fill (+ diag 1.0 for l<256): 2048 units of 8 rows, unit u = gw.
    // ns copy (l<256 half): 256 units of 32 rows, owned by gw >= 1792.
    if (att) {
        int r0 = gw * 8;
        #pragma unroll
        for (int k = 0; k < 8; k++) {
            int row = r0 + k;                   // row = b*512 + l
            int l = row & 511;
            size_t base = (size_t)row * 192;
            int c = l >> 2;                     // identity float4 col (valid when l<256)
            #pragma unroll
            for (int k2 = 0; k2 < 6; k2++) {
                float4 v = make_float4(0.f, 0.f, 0.f, 0.f);
                if (l < 256 && (k2 * 32 + lane) == c)
                    ((float*)&v)[l & 3] = 1.0f;
                ((float4*)att)[base + k2 * 32 + lane] = v;
            }
        }
    }
    if (ns) {
        if (att) {
            if (gw >= 1792) {
                int re0 = (gw - 1792) * 32;     // (b*EN+e) row base
                #pragma unroll 4
                for (int m = 0; m < 32; m++) {
                    size_t rb = (size_t)(re0 + m) * 128;
                    float4 a0 = ((const float4*)state)[rb + lane];
                    float4 a1 = ((const float4*)state)[rb + lane + 32];
                    ((float4*)ns)[rb + lane]      = a0;
                    ((float4*)ns)[rb + lane + 32] = a1;
                }
            }
        } else {
            // ns-only output: block bid owns unit bid; each warp copies 4 rows
            int re0 = bid * 32 + wid * 4;
            #pragma unroll
            for (int m = 0; m < 4; m++) {
                size_t rb = (size_t)(re0 + m) * 128;
                float4 a0 = ((const float4*)state)[rb + lane];
                float4 a1 = ((const float4*)state)[rb + lane + 32];
                float4 a2 = ((const float4*)state)[rb + lane + 64];
                float4 a3 = ((const float4*)state)[rb + lane + 96];
                ((float4*)ns)[rb + lane]      = a0;
                ((float4*)ns)[rb + lane + 32] = a1;
                ((float4*)ns)[rb + lane + 64] = a2;
                ((float4*)ns)[rb + lane + 96] = a3;
            }
        }
    }
    gridbar(1, bid, tid);

    // ================= Phase 1: GQT (all blocks) + GPb (blocks 248..255) =============
    {
        int h = bid >> 5, et = bid & 31;    // e tile of 8
        float* wks = sm.gk;                 // [8 ee][32 d]
        {
            int ee = wid, d = lane;
            wks[ee * 32 + d] = Wk[(h * 32 + d) * DM + et * 8 + ee];
        }
        __syncthreads();

        float4 q4[8];
        const float4* q0p = (const float4*)(g_Q0 + (size_t)tid * DM + h * 32);
        #pragma unroll
        for (int j = 0; j < 8; j++) q4[j] = q0p[j];

        #pragma unroll
        for (int ee = 0; ee < 8; ee++) {
            float acc = 0.0f;
            const float4* wr = (const float4*)&wks[ee * 32];
            #pragma unroll
            for (int j = 0; j < 8; j++) {
                float4 w4 = wr[j];
                acc += q4[j].x * w4.x + q4[j].y * w4.y + q4[j].z * w4.z + q4[j].w * w4.w;
            }
            g_GQT[(h * DM + et * 8 + ee) * LQ + tid] = acc;
        }
        __syncthreads();

        if (bid >= 248) {
            int hh = bid - 248;              // head for GPb
            float* wk  = sm.gk;              // [32 d][256 e]
            float* p0s = sm.gk + 8192;       // [32 b][32 d]
            #pragma unroll
            for (int d = 0; d < 32; d++)
                wk[d * 256 + tid] = Wk[(hh * 32 + d) * DM + tid];
            #pragma unroll
            for (int k = 0; k < 4; k++) {
                int lin = k * 256 + tid;
                int b = lin >> 5, d = lin & 31;
                p0s[b * 32 + d] = g_P0[b * DM + hh * 32 + d];
            }
            __syncthreads();
            #pragma unroll 4
            for (int b = 0; b < 32; b++) {
                float acc = 0.0f;
                #pragma unroll
                for (int d = 0; d < 32; d++)
                    acc = fmaf(p0s[b * 32 + d], wk[d * 256 + tid], acc);
                g_GPb[(b * H + hh) * DM + tid] = acc;
            }
        }
    }
    gridbar(2, bid, tid);

    // ================= Phase 2: delta + weight-dependent outputs =====================
    {
        int b  = bid >> 3;                   // batch 0..31
        int lt = bid & 7;                    // l' tile (32 l')

        #pragma unroll
        for (int k = 0; k < 8; k++)
            sm.d.gps[k * 256 + tid] = g_GPb[(size_t)b * H * DM + k * 256 + tid];
        __syncthreads();

        // sgp[h] = sum_e gps[h][e] : warp w handles h=w
        {
            float part = 0.0f;
            #pragma unroll
            for (int k = 0; k < 8; k++) part += sm.d.gps[wid * 256 + lane + 32 * k];
            #pragma unroll
            for (int off = 16; off > 0; off >>= 1)
                part += __shfl_down_sync(0xffffffffu, part, off);
            if (lane == 0) sm.d.sgp[wid] = part;
        }

        int lp = lt * 32 + lane;
        int l = 256 + lp;

        float sdg[8], sgq[8];
        #pragma unroll
        for (int h = 0; h < 8; h++) { sdg[h] = 0.0f; sgq[h] = 0.0f; }
        float sd = 0.0f;

        const float* st = state + (size_t)b * EN * DX;
        const float* ob = obs   + (size_t)b * EN * DZ;

        #pragma unroll 4
        for (int j = 0; j < 32; j++) {
            int e = wid * 32 + j;
            float D = st[(size_t)e * DX + l] - ob[(size_t)e * DZ + lp];
            sd += D;
            #pragma unroll
            for (int h = 0; h < 8; h++) {
                float g = g_GQT[(h * DM + e) * LQ + lp];
                sgq[h] += g;
                sdg[h] = fmaf(D, g + sm.d.gps[h * DM + e], sdg[h]);
            }
        }

        #pragma unroll
        for (int h = 0; h < 8; h++) {
            sm.d.red[h * 256 + tid]       = sdg[h];
            sm.d.red[(8 + h) * 256 + tid] = sgq[h];
        }
        sm.d.red[16 * 256 + tid] = sd;
        __syncthreads();

        if (tid < 32) {
            int lo2 = tid;
            int lp2 = lt * 32 + lo2;
            int l2 = 256 + lp2;
            float sdt = 0.0f;
            #pragma unroll
            for (int q = 0; q < 8; q++) sdt += sm.d.red[16 * 256 + q * 32 + lo2];
            float md = sdt * (1.0f / 256.0f);
            float wsum = 0.0f;
            #pragma unroll
            for (int h = 0; h < 8; h++) {
                float sdgt = 0.0f, sq = 0.0f;
                #pragma unroll
                for (int q = 0; q < 8; q++) {
                    sdgt += sm.d.red[h * 256 + q * 32 + lo2];
                    sq   += sm.d.red[(8 + h) * 256 + q * 32 + lo2];
                }
                float sg = sq + sm.d.sgp[h];
                float delta = (sdgt - md * sg) * 0.17677669529663688f;   // 1/sqrt(32)
                wsum += 1.0f / (1.0f + expf(-delta));
            }
            float w = wsum * 0.125f;
            sm.d.wsh[lo2] = w;
            if (att) {
                size_t rowbase = ((size_t)(b * 512 + l2)) * 768;
                att[rowbase + l2]       = w;          // state key
                att[rowbase + l2 + 256] = 1.0f - w;   // obs key
            }
        }
        __syncthreads();

        // fused new_state for l >= 256 (columns are L1-hot from the delta loop)
        if (ns != nullptr) {
            float w = sm.d.wsh[lane];
            float* n = ns + (size_t)b * EN * DX;
            #pragma unroll 4
            for (int j = 0; j < 32; j++) {
                int e = wid * 32 + j;
                float s = st[(size_t)e * DX + l], o = ob[(size_t)e * DZ + lp];
                n[(size_t)e * DX + l] = o + w * (s - o);
            }
        }
    }

    // ================= Finalize: flag-based completion + reset by block 0 ============
    __syncthreads();
    if (bid == 0) {
        if (tid == 0) { __threadfence(); g_flags[0] = 3u; }
        while (g_flags[tid * 32] < 3u) __nanosleep(32);
        __syncthreads();
        // all blocks done (their final action was the flag store) -> reset for replay
        g_flags[tid * 32] = 0u;
        if (tid == 0) { g_release = 0u; __threadfence(); }
    } else {
        if (tid == 0) { __threadfence(); g_flags[bid * 32] = 3u; }
    }
}

// ----------------------------------------------------------------
extern "C" void kernel_launch(void* const* d_in, const int* in_sizes, int n_in,
                              void* d_out, int out_size) {
    const float* state = (const float*)d_in[0];
    const float* obs   = (const float*)d_in[1];
    const float* Qp    = (const float*)d_in[2];
    const float* Wq    = (const float*)d_in[3];
    const float* bq    = (const float*)d_in[4];
    const float* Wk    = (const float*)d_in[5];
    // bk (d_in[6]) provably cancels in the masked softmax — unused.
    float* out = (float*)d_out;

    const int NS = B * EN * DX;        // 4,194,304
    const int AT = B * DX * (DX + DZ); // 12,582,912

    float* ns  = nullptr;
    float* att = nullptr;
    if (out_size >= NS + AT)      { ns = out; att = out + NS; }
    else if (out_size == AT)      { att = out; }
    else                          { ns = out; }

    k_fused<<<NB, 256>>>(state, obs, Qp, Wq, bq, Wk, ns, att);
}